// round 6
// baseline (speedup 1.0000x reference)
#include <cuda_runtime.h>

#define WL_L      2048
#define WL_LMASK  2047
#define WL_D      32
#define WL_B      16
#define WL_NT     256

#define WL_G      4                   // d-planes per CTA
#define WL_T      256                 // outputs per plane per CTA
#define WL_HALO   112                 // >= 105 back-reach, multiple of 4
#define WL_EXT    (WL_T + WL_HALO)    // 368
#define WL_NCHUNK (WL_L / WL_T)       // 8
#define WL_NDG    (WL_D / WL_G)       // 8
#define WL_PT     (WL_NT / WL_G)      // 64 threads per plane

__global__ __launch_bounds__(WL_NT, 7) void wavelet_db4_kernel(
    const float* __restrict__ x,       // (B, L, D)
    const float* __restrict__ w_dec,   // (4, L, L) — only 8 taps read
    const float* __restrict__ v_dec,   // (4, L, L) — only 8 taps read
    float* __restrict__ out)           // (B, D, L, 5)
{
    __shared__ float xs [WL_G][WL_EXT];
    __shared__ float v0s[WL_G][WL_EXT];
    __shared__ float v1s[WL_G][WL_EXT];
    __shared__ float v2s[WL_G][WL_EXT];
    __shared__ float gs[8];
    __shared__ float hs[8];

    const int tid   = threadIdx.x;
    const int blk   = blockIdx.x;
    const int chunk = blk & (WL_NCHUNK - 1);
    const int dg    = (blk >> 3) & (WL_NDG - 1);
    const int b     = blk >> 6;
    const int M0    = chunk * WL_T;
    const int base  = M0 - WL_HALO;

    const int p = tid >> 6;           // plane 0..3
    const int q = tid & (WL_PT - 1);  // slot in plane 0..63

    // halo side-job: 28 halo quads split 14/14 across the plane's two warps
    int hq = -1;
    if (q >= 18 && q < 32)      hq = q - 18;   // 0..13  (warp A lanes 18-31)
    else if (q >= 50)           hq = q - 36;   // 14..27 (warp B lanes 18-31)

    // taps from row 0 of level-0 filters: f[0][0][(0-i) mod L] = tap[i]
    if (tid < 8) {
        int col = (WL_L - tid) & WL_LMASK;
        gs[tid] = v_dec[col];
        hs[tid] = w_dec[col];
    }

    // amortized gather: one float4 across 4 adjacent d per x-row
    {
        const float* xp = x + ((size_t)b * WL_L * WL_D) + dg * WL_G;
        for (int l = tid; l < WL_EXT; l += WL_NT) {
            int gl = (base + l) & WL_LMASK;
            float4 qv = *(const float4*)(xp + (size_t)gl * WL_D);
            xs[0][l] = qv.x; xs[1][l] = qv.y; xs[2][l] = qv.z; xs[3][l] = qv.w;
        }
    }
    __syncthreads();

    float g[8], h[8];
    #pragma unroll
    for (int i = 0; i < 8; i++) { g[i] = gs[i]; h[i] = hs[i]; }

    const float4* xs4  = (const float4*)(&xs [p][0]);
    const float4* v0s4 = (const float4*)(&v0s[p][0]);
    const float4* v1s4 = (const float4*)(&v1s[p][0]);
    const float4* v2s4 = (const float4*)(&v2s[p][0]);
    float4* v0s4w = (float4*)(&v0s[p][0]);
    float4* v1s4w = (float4*)(&v1s[p][0]);
    float4* v2s4w = (float4*)(&v2s[p][0]);

    const int l0 = WL_HALO + 4 * q;   // this thread's output quad
    const int b4 = l0 >> 2;           // 28 + q

    float w0[4], w1[4], w2[4];

    // ── stage 1: dilation 1 on xs → v0 (g) + w0 (h), window loaded once
    {
        int wb = b4 - 2;              // (l0-8)>>2
        float4 a = xs4[wb], bb = xs4[wb + 1], c = xs4[wb + 2];
        float win[12] = {a.x,a.y,a.z,a.w, bb.x,bb.y,bb.z,bb.w, c.x,c.y,c.z,c.w};
        float vg[4] = {0,0,0,0}; float vh[4] = {0,0,0,0};
        #pragma unroll
        for (int i = 0; i < 8; i++) {
            #pragma unroll
            for (int j = 0; j < 4; j++) {
                vg[j] += g[i] * win[8 + j - i];
                vh[j] += h[i] * win[8 + j - i];
            }
        }
        v0s4w[b4] = make_float4(vg[0], vg[1], vg[2], vg[3]);
        #pragma unroll
        for (int j = 0; j < 4; j++) w0[j] = vh[j];

        if (hq >= 2) {                // halo v0 (g only), valid l0h >= 8
            int hl0 = 4 * hq, wbh = (hl0 - 8) >> 2;
            float4 ha = xs4[wbh], hb = xs4[wbh + 1], hc = xs4[wbh + 2];
            float hw[12] = {ha.x,ha.y,ha.z,ha.w, hb.x,hb.y,hb.z,hb.w, hc.x,hc.y,hc.z,hc.w};
            float a0=0.f, a1=0.f, a2=0.f, a3=0.f;
            #pragma unroll
            for (int i = 0; i < 8; i++) {
                a0 += g[i] * hw[ 8 - i]; a1 += g[i] * hw[ 9 - i];
                a2 += g[i] * hw[10 - i]; a3 += g[i] * hw[11 - i];
            }
            v0s4w[hq] = make_float4(a0, a1, a2, a3);
        }
    }
    __syncthreads();

    // ── stage 2: dilation 2 on v0 → v1 (g) + w1 (h)
    {
        int wb = b4 - 4;              // (l0-16)>>2
        float win[20];
        #pragma unroll
        for (int kk = 0; kk < 5; kk++) {
            float4 qv = v0s4[wb + kk];
            win[4*kk] = qv.x; win[4*kk+1] = qv.y; win[4*kk+2] = qv.z; win[4*kk+3] = qv.w;
        }
        float vg[4] = {0,0,0,0}; float vh[4] = {0,0,0,0};
        #pragma unroll
        for (int i = 0; i < 8; i++) {
            #pragma unroll
            for (int j = 0; j < 4; j++) {
                vg[j] += g[i] * win[16 + j - 2*i];
                vh[j] += h[i] * win[16 + j - 2*i];
            }
        }
        v1s4w[b4] = make_float4(vg[0], vg[1], vg[2], vg[3]);
        #pragma unroll
        for (int j = 0; j < 4; j++) w1[j] = vh[j];

        if (hq >= 7) {                // halo v1 (g only), valid l0h >= 28
            int hl0 = 4 * hq, wbh = (hl0 - 16) >> 2;
            float hw[20];
            #pragma unroll
            for (int kk = 0; kk < 5; kk++) {
                float4 qv = v0s4[wbh + kk];
                hw[4*kk] = qv.x; hw[4*kk+1] = qv.y; hw[4*kk+2] = qv.z; hw[4*kk+3] = qv.w;
            }
            float a0=0.f, a1=0.f, a2=0.f, a3=0.f;
            #pragma unroll
            for (int i = 0; i < 8; i++) {
                a0 += g[i] * hw[16 - 2*i]; a1 += g[i] * hw[17 - 2*i];
                a2 += g[i] * hw[18 - 2*i]; a3 += g[i] * hw[19 - 2*i];
            }
            v1s4w[hq] = make_float4(a0, a1, a2, a3);
        }
    }
    __syncthreads();

    // ── stage 3: dilation 4 on v1 → v2 (g) + w2 (h); one float4 per tap
    {
        float vg[4] = {0,0,0,0}; float vh[4] = {0,0,0,0};
        #pragma unroll
        for (int i = 0; i < 8; i++) {
            float4 qv = v1s4[b4 - i];
            vg[0] += g[i] * qv.x; vg[1] += g[i] * qv.y;
            vg[2] += g[i] * qv.z; vg[3] += g[i] * qv.w;
            vh[0] += h[i] * qv.x; vh[1] += h[i] * qv.y;
            vh[2] += h[i] * qv.z; vh[3] += h[i] * qv.w;
        }
        v2s4w[b4] = make_float4(vg[0], vg[1], vg[2], vg[3]);
        #pragma unroll
        for (int j = 0; j < 4; j++) w2[j] = vh[j];

        if (hq >= 14) {               // halo v2 (g only), valid l0h >= 56
            int hb4 = hq;
            float a0=0.f, a1=0.f, a2=0.f, a3=0.f;
            #pragma unroll
            for (int i = 0; i < 8; i++) {
                float4 qv = v1s4[hb4 - i];
                a0 += g[i] * qv.x; a1 += g[i] * qv.y;
                a2 += g[i] * qv.z; a3 += g[i] * qv.w;
            }
            v2s4w[hq] = make_float4(a0, a1, a2, a3);
        }
    }
    __syncthreads();

    // ── stage 4: dilation 8 on v2 → w3 (h) + v3 (g); write all 5 coeffs
    {
        float w3[4] = {0,0,0,0}, v3[4] = {0,0,0,0};
        #pragma unroll
        for (int i = 0; i < 8; i++) {
            float4 qv = v2s4[b4 - 2*i];
            w3[0] += h[i] * qv.x; w3[1] += h[i] * qv.y;
            w3[2] += h[i] * qv.z; w3[3] += h[i] * qv.w;
            v3[0] += g[i] * qv.x; v3[1] += g[i] * qv.y;
            v3[2] += g[i] * qv.z; v3[3] += g[i] * qv.w;
        }

        float o[20];
        #pragma unroll
        for (int j = 0; j < 4; j++) {
            o[j*5 + 0] = w0[j];
            o[j*5 + 1] = w1[j];
            o[j*5 + 2] = w2[j];
            o[j*5 + 3] = w3[j];
            o[j*5 + 4] = v3[j];
        }
        const int bd = b * WL_D + dg * WL_G + p;
        const int m0 = M0 + 4 * q;
        float4* og = (float4*)(out + ((size_t)bd * WL_L + m0) * 5);
        #pragma unroll
        for (int kk = 0; kk < 5; kk++) og[kk] = ((const float4*)o)[kk];
    }
}

extern "C" void kernel_launch(void* const* d_in, const int* in_sizes, int n_in,
                              void* d_out, int out_size) {
    const float* x     = (const float*)d_in[0];
    const float* w_dec = (const float*)d_in[1];
    const float* v_dec = (const float*)d_in[2];
    float* out = (float*)d_out;

    wavelet_db4_kernel<<<WL_B * WL_NDG * WL_NCHUNK, WL_NT>>>(x, w_dec, v_dec, out);
}

// round 7
// speedup vs baseline: 1.2651x; 1.2651x over previous
#include <cuda_runtime.h>

#define WL_L      2048
#define WL_LMASK  2047
#define WL_D      32
#define WL_B      16
#define WL_NT     128                 // 4 warps, one per d-plane

#define WL_G      4                   // d-planes per CTA
#define WL_T      256                 // outputs per plane per CTA
#define WL_HALO   112                 // >= 105 back-reach, multiple of 4
#define WL_EXT    (WL_T + WL_HALO)    // 368 (92 quads)
#define WL_NCHUNK (WL_L / WL_T)       // 8
#define WL_NDG    (WL_D / WL_G)       // 8

__global__ __launch_bounds__(WL_NT) void wavelet_db4_kernel(
    const float* __restrict__ x,       // (B, L, D)
    const float* __restrict__ w_dec,   // (4, L, L) — only 8 taps read
    const float* __restrict__ v_dec,   // (4, L, L) — only 8 taps read
    float* __restrict__ out)           // (B, D, L, 5)
{
    __shared__ float xs [WL_G][WL_EXT];
    __shared__ float v0s[WL_G][WL_EXT];
    __shared__ float v1s[WL_G][WL_EXT];
    __shared__ float v2s[WL_G][WL_EXT];
    __shared__ float gs[8];
    __shared__ float hs[8];

    const int tid   = threadIdx.x;
    const int blk   = blockIdx.x;
    const int chunk = blk & (WL_NCHUNK - 1);
    const int dg    = (blk >> 3) & (WL_NDG - 1);
    const int b     = blk >> 6;
    const int M0    = chunk * WL_T;
    const int base  = M0 - WL_HALO;

    const int p    = tid >> 5;        // plane 0..3 == warp id
    const int lane = tid & 31;

    // halo side-job: 28 halo quads → lanes 4..31 (hq = lane-4, 0..27)
    const int hq = lane - 4;

    // taps from row 0 of level-0 filters: f[0][0][(0-i) mod L] = tap[i]
    if (tid < 8) {
        int col = (WL_L - tid) & WL_LMASK;
        gs[tid] = v_dec[col];
        hs[tid] = w_dec[col];
    }

    // amortized gather: one float4 across 4 adjacent d per x-row (all threads)
    {
        const float* xp = x + ((size_t)b * WL_L * WL_D) + dg * WL_G;
        #pragma unroll
        for (int l = tid; l < WL_EXT; l += WL_NT) {
            int gl = (base + l) & WL_LMASK;
            float4 qv = *(const float4*)(xp + (size_t)gl * WL_D);
            xs[0][l] = qv.x; xs[1][l] = qv.y; xs[2][l] = qv.z; xs[3][l] = qv.w;
        }
    }
    __syncthreads();   // the ONLY CTA-wide barrier

    float g[8], h[8];
    #pragma unroll
    for (int i = 0; i < 8; i++) { g[i] = gs[i]; h[i] = hs[i]; }

    const float4* xs4  = (const float4*)(&xs [p][0]);
    const float4* v0s4 = (const float4*)(&v0s[p][0]);
    const float4* v1s4 = (const float4*)(&v1s[p][0]);
    const float4* v2s4 = (const float4*)(&v2s[p][0]);
    float4* v0s4w = (float4*)(&v0s[p][0]);
    float4* v1s4w = (float4*)(&v1s[p][0]);
    float4* v2s4w = (float4*)(&v2s[p][0]);

    // two output quads per thread: quad indices 28+lane and 60+lane
    int b4s[2]; b4s[0] = 28 + lane; b4s[1] = 60 + lane;

    float w0[2][4], w1[2][4], w2[2][4];

    // ── stage 1: dilation 1 on xs → v0 (g) + w0 (h)
    #pragma unroll
    for (int s = 0; s < 2; s++) {
        int b4 = b4s[s];
        int wb = b4 - 2;
        float4 a = xs4[wb], bb = xs4[wb + 1], c = xs4[wb + 2];
        float win[12] = {a.x,a.y,a.z,a.w, bb.x,bb.y,bb.z,bb.w, c.x,c.y,c.z,c.w};
        float vg[4] = {0,0,0,0};
        #pragma unroll
        for (int i = 0; i < 8; i++) {
            #pragma unroll
            for (int j = 0; j < 4; j++) {
                vg[j]    += g[i] * win[8 + j - i];
                w0[s][j] = (i == 0) ? h[0] * win[8 + j]
                                    : w0[s][j] + h[i] * win[8 + j - i];
            }
        }
        v0s4w[b4] = make_float4(vg[0], vg[1], vg[2], vg[3]);
    }
    if (hq >= 2) {                    // halo v0 (g only), l0h >= 8
        int wbh = hq - 2;
        float4 ha = xs4[wbh], hb = xs4[wbh + 1], hc = xs4[wbh + 2];
        float hw[12] = {ha.x,ha.y,ha.z,ha.w, hb.x,hb.y,hb.z,hb.w, hc.x,hc.y,hc.z,hc.w};
        float a0=0.f, a1=0.f, a2=0.f, a3=0.f;
        #pragma unroll
        for (int i = 0; i < 8; i++) {
            a0 += g[i] * hw[ 8 - i]; a1 += g[i] * hw[ 9 - i];
            a2 += g[i] * hw[10 - i]; a3 += g[i] * hw[11 - i];
        }
        v0s4w[hq] = make_float4(a0, a1, a2, a3);
    }
    __syncwarp();

    // ── stage 2: dilation 2 on v0 → v1 (g) + w1 (h)
    #pragma unroll
    for (int s = 0; s < 2; s++) {
        int b4 = b4s[s];
        int wb = b4 - 4;
        float win[20];
        #pragma unroll
        for (int kk = 0; kk < 5; kk++) {
            float4 qv = v0s4[wb + kk];
            win[4*kk] = qv.x; win[4*kk+1] = qv.y; win[4*kk+2] = qv.z; win[4*kk+3] = qv.w;
        }
        float vg[4] = {0,0,0,0};
        #pragma unroll
        for (int i = 0; i < 8; i++) {
            #pragma unroll
            for (int j = 0; j < 4; j++) {
                vg[j]    += g[i] * win[16 + j - 2*i];
                w1[s][j] = (i == 0) ? h[0] * win[16 + j]
                                    : w1[s][j] + h[i] * win[16 + j - 2*i];
            }
        }
        v1s4w[b4] = make_float4(vg[0], vg[1], vg[2], vg[3]);
    }
    if (hq >= 7) {                    // halo v1 (g only), l0h >= 28
        int wbh = hq - 4;
        float hw[20];
        #pragma unroll
        for (int kk = 0; kk < 5; kk++) {
            float4 qv = v0s4[wbh + kk];
            hw[4*kk] = qv.x; hw[4*kk+1] = qv.y; hw[4*kk+2] = qv.z; hw[4*kk+3] = qv.w;
        }
        float a0=0.f, a1=0.f, a2=0.f, a3=0.f;
        #pragma unroll
        for (int i = 0; i < 8; i++) {
            a0 += g[i] * hw[16 - 2*i]; a1 += g[i] * hw[17 - 2*i];
            a2 += g[i] * hw[18 - 2*i]; a3 += g[i] * hw[19 - 2*i];
        }
        v1s4w[hq] = make_float4(a0, a1, a2, a3);
    }
    __syncwarp();

    // ── stage 3: dilation 4 on v1 → v2 (g) + w2 (h)
    #pragma unroll
    for (int s = 0; s < 2; s++) {
        int b4 = b4s[s];
        float vg[4] = {0,0,0,0};
        #pragma unroll
        for (int i = 0; i < 8; i++) {
            float4 qv = v1s4[b4 - i];
            vg[0] += g[i] * qv.x; vg[1] += g[i] * qv.y;
            vg[2] += g[i] * qv.z; vg[3] += g[i] * qv.w;
            if (i == 0) {
                w2[s][0] = h[0] * qv.x; w2[s][1] = h[0] * qv.y;
                w2[s][2] = h[0] * qv.z; w2[s][3] = h[0] * qv.w;
            } else {
                w2[s][0] += h[i] * qv.x; w2[s][1] += h[i] * qv.y;
                w2[s][2] += h[i] * qv.z; w2[s][3] += h[i] * qv.w;
            }
        }
        v2s4w[b4] = make_float4(vg[0], vg[1], vg[2], vg[3]);
    }
    if (hq >= 14) {                   // halo v2 (g only), l0h >= 56
        float a0=0.f, a1=0.f, a2=0.f, a3=0.f;
        #pragma unroll
        for (int i = 0; i < 8; i++) {
            float4 qv = v1s4[hq - i];
            a0 += g[i] * qv.x; a1 += g[i] * qv.y;
            a2 += g[i] * qv.z; a3 += g[i] * qv.w;
        }
        v2s4w[hq] = make_float4(a0, a1, a2, a3);
    }
    __syncwarp();

    // ── stage 4: dilation 8 on v2 → w3 (h) + v3 (g); write all 5 coeffs
    const int bd = b * WL_D + dg * WL_G + p;
    #pragma unroll
    for (int s = 0; s < 2; s++) {
        int b4 = b4s[s];
        float w3[4] = {0,0,0,0}, v3[4] = {0,0,0,0};
        #pragma unroll
        for (int i = 0; i < 8; i++) {
            float4 qv = v2s4[b4 - 2*i];
            w3[0] += h[i] * qv.x; w3[1] += h[i] * qv.y;
            w3[2] += h[i] * qv.z; w3[3] += h[i] * qv.w;
            v3[0] += g[i] * qv.x; v3[1] += g[i] * qv.y;
            v3[2] += g[i] * qv.z; v3[3] += g[i] * qv.w;
        }

        float o[20];
        #pragma unroll
        for (int j = 0; j < 4; j++) {
            o[j*5 + 0] = w0[s][j];
            o[j*5 + 1] = w1[s][j];
            o[j*5 + 2] = w2[s][j];
            o[j*5 + 3] = w3[j];
            o[j*5 + 4] = v3[j];
        }
        const int m0 = M0 + 4 * (b4 - 28);   // = M0 + (l0 - HALO)
        float4* og = (float4*)(out + ((size_t)bd * WL_L + m0) * 5);
        #pragma unroll
        for (int kk = 0; kk < 5; kk++) og[kk] = ((const float4*)o)[kk];
    }
}

extern "C" void kernel_launch(void* const* d_in, const int* in_sizes, int n_in,
                              void* d_out, int out_size) {
    const float* x     = (const float*)d_in[0];
    const float* w_dec = (const float*)d_in[1];
    const float* v_dec = (const float*)d_in[2];
    float* out = (float*)d_out;

    wavelet_db4_kernel<<<WL_B * WL_NDG * WL_NCHUNK, WL_NT>>>(x, w_dec, v_dec, out);
}